// round 12
// baseline (speedup 1.0000x reference)
#include <cuda_runtime.h>
#include <cstdint>

#define Dd 128
#define NMAX 50000
#define EMAX 1000000
#define PADW 136   // W smem row stride (words); conflict-free per half-warp phase

// Scratch (static device globals -- no allocation allowed)
__device__ float g_u[NMAX * Dd];
__device__ float g_h[NMAX * Dd];
__device__ float g_dinv[NMAX];
__device__ float g_wt[4][Dd * Dd];   // transposed + tf32 + k-permuted weights [N][K']
__device__ int   g_cnt[NMAX];        // zeroed by scan after use (and by module init)
__device__ int   g_deg[NMAX];
__device__ int   g_offs[NMAX];
__device__ int   g_cur[NMAX];
__device__ int   g_csr[EMAX];
__device__ volatile int g_sstat[256];  // 0 invalid, 1 agg ready, 2 prefix ready
__device__ volatile int g_sagg[256];   // block aggregate (write-once)
__device__ volatile int g_spre[256];   // inclusive prefix (write-once)

__device__ __forceinline__ uint32_t f2tf32(float v) {
    uint32_t r;
    asm("cvt.rna.tf32.f32 %0, %1;" : "=r"(r) : "f"(v));
    return r;
}

__device__ __forceinline__ void mma_tf32(float c[4], uint32_t a0, uint32_t a1,
                                         uint32_t a2, uint32_t a3,
                                         uint32_t b0, uint32_t b1) {
    asm volatile(
        "mma.sync.aligned.m16n8k8.row.col.f32.tf32.tf32.f32 "
        "{%0,%1,%2,%3}, {%4,%5,%6,%7}, {%8,%9}, {%0,%1,%2,%3};"
        : "+f"(c[0]), "+f"(c[1]), "+f"(c[2]), "+f"(c[3])
        : "r"(a0), "r"(a1), "r"(a2), "r"(a3), "r"(b0), "r"(b1));
}

__device__ __forceinline__ int warp_iscan(int v, int lane) {
#pragma unroll
    for (int d = 1; d < 32; d <<= 1) {
        int t = __shfl_up_sync(0xffffffff, v, d);
        if (lane >= d) v += t;
    }
    return v;
}

__device__ __forceinline__ float4 ldg4z(const float* p, bool v) {
    if (v) return __ldg((const float4*)p);
    return make_float4(0.f, 0.f, 0.f, 0.f);
}

// ---------------------------------------------------------------------------
// Persistent tf32 mma.sync GEMM. A loaded as float4 per 16-k supergroup
// (coalesced LDG.128, pipelined one supergroup ahead); W smem pre-permuted.
//  mode 0: aux=dinv -> C = val*dinv[row]
//  mode 1: aux=bias -> C = relu(val + bias)
//  nheads==2: block parity selects (Wt1,aux1,C1)
// ---------------------------------------------------------------------------
__global__ void __launch_bounds__(256, 2) k_mma_gemm(
    const float* __restrict__ A,
    const float* __restrict__ Wt0, const float* __restrict__ aux0, float* __restrict__ C0,
    const float* Wt1, const float* aux1, float* C1,
    int n, int mode, int nheads)
{
    extern __shared__ float sm[];
    uint32_t* Wsu = (uint32_t*)sm;   // [128][PADW]

    int tid  = threadIdx.x;
    int wid  = tid >> 5;
    int lane = tid & 31;

    int ntiles = (n + 127) >> 7;
    int tile0, tstep;
    const float* Wt; const float* aux; float* C;
    if (nheads == 2) {
        int head = blockIdx.x & 1;
        tile0 = blockIdx.x >> 1;
        tstep = gridDim.x >> 1;
        Wt = head ? Wt1 : Wt0; aux = head ? aux1 : aux0; C = head ? C1 : C0;
    } else {
        tile0 = blockIdx.x;
        tstep = gridDim.x;
        Wt = Wt0; aux = aux0; C = C0;
    }

    const uint4* Wt4 = (const uint4*)Wt;
#pragma unroll
    for (int i = 0; i < 16; i++) {
        int f = tid + i * 256;
        int r = f >> 5, j = (f & 31) << 2;
        *(uint4*)(Wsu + r * PADW + j) = Wt4[f];
    }
    __syncthreads();

    int kq  = lane & 3;
    int bn0 = lane >> 2;

    for (int tile = tile0; tile < ntiles; tile += tstep) {
        int row0 = tile << 7;
        int r0 = row0 + wid * 16 + (lane >> 2);
        int r1 = r0 + 8;
        bool v0 = r0 < n, v1 = r1 < n;
        const float* a0p = A + (size_t)r0 * 128 + (kq << 2);
        const float* a1p = a0p + 8 * 128;

        float c[16][4];
#pragma unroll
        for (int nt = 0; nt < 16; nt++)
#pragma unroll
            for (int q = 0; q < 4; q++) c[nt][q] = 0.0f;

        float4 fA = ldg4z(a0p, v0);
        float4 fB = ldg4z(a1p, v1);

#pragma unroll
        for (int G = 0; G < 8; G++) {
            float4 nA, nB;
            if (G < 7) {
                nA = ldg4z(a0p + (G + 1) * 16, v0);
                nB = ldg4z(a1p + (G + 1) * 16, v1);
            }
            uint32_t a00 = f2tf32(fA.x), a10 = f2tf32(fB.x);
            uint32_t a20 = f2tf32(fA.y), a30 = f2tf32(fB.y);
            uint32_t a01 = f2tf32(fA.z), a11 = f2tf32(fB.z);
            uint32_t a21 = f2tf32(fA.w), a31 = f2tf32(fB.w);
            int gbase = G * 16 + (kq << 1);
#pragma unroll
            for (int nt = 0; nt < 16; nt++) {
                const uint32_t* wr = Wsu + (nt * 8 + bn0) * PADW + gbase;
                uint2 b0 = *(const uint2*)wr;
                uint2 b1 = *(const uint2*)(wr + 8);
                mma_tf32(c[nt], a00, a10, a20, a30, b0.x, b0.y);
                mma_tf32(c[nt], a01, a11, a21, a31, b1.x, b1.y);
            }
            fA = nA; fB = nB;
        }

        int cc = kq * 2;
        if (mode == 0) {
            float d0 = v0 ? aux[r0] : 0.0f;
            float d1 = v1 ? aux[r1] : 0.0f;
#pragma unroll
            for (int nt = 0; nt < 16; nt++) {
                int col = nt * 8 + cc;
                if (v0)
                    *(float2*)(C + (size_t)r0 * 128 + col) =
                        make_float2(c[nt][0] * d0, c[nt][1] * d0);
                if (v1)
                    *(float2*)(C + (size_t)r1 * 128 + col) =
                        make_float2(c[nt][2] * d1, c[nt][3] * d1);
            }
        } else {
#pragma unroll
            for (int nt = 0; nt < 16; nt++) {
                int col = nt * 8 + cc;
                float2 bb = *(const float2*)(aux + col);
                if (v0)
                    *(float2*)(C + (size_t)r0 * 128 + col) =
                        make_float2(fmaxf(c[nt][0] + bb.x, 0.f), fmaxf(c[nt][1] + bb.y, 0.f));
                if (v1)
                    *(float2*)(C + (size_t)r1 * 128 + col) =
                        make_float2(fmaxf(c[nt][2] + bb.x, 0.f), fmaxf(c[nt][3] + bb.y, 0.f));
            }
        }
    }
}

// ---------------------------------------------------------------------------
// fused weight-prep + degree histogram. cnt[] arrives zeroed (module init on
// call 1; reset by k_scan_lb on every call thereafter).
// W perm within 16-group: kq=(k>>2)&3, s=(k>>1)&1, t=k&1 -> (s<<3)|(kq<<1)|t
// ---------------------------------------------------------------------------
__global__ void k_prep_hist(const float* __restrict__ W0, const float* __restrict__ W1,
                            const float* __restrict__ W2, const float* __restrict__ W3,
                            float* __restrict__ Wt,
                            const int* __restrict__ dst, int* __restrict__ cnt,
                            int E, int n) {
    int i = blockIdx.x * blockDim.x + threadIdx.x;
    if (i < 4 * Dd * Dd) {
        int w = i >> 14, r = i & (Dd * Dd - 1);
        const float* W = (w == 0) ? W0 : (w == 1) ? W1 : (w == 2) ? W2 : W3;
        int k = r >> 7, nn = r & 127;
        int kp = (k & ~15) | (((k >> 1) & 1) << 3) | (((k >> 2) & 3) << 1) | (k & 1);
        ((uint32_t*)Wt)[w * Dd * Dd + nn * Dd + kp] = f2tf32(W[k * Dd + nn]);
    }
    if (i < E) {
        int d = dst[i];
        if ((unsigned)d < (unsigned)n) atomicAdd(&cnt[d], 1);
    }
}

// ---------------------------------------------------------------------------
// Single-pass exclusive scan, decoupled lookback with WRITE-ONCE slots:
// aggregate goes to g_sagg, inclusive prefix to g_spre -- a reader that saw
// status==1 can never accidentally consume a prefix (no overwrite race).
// Also emits deg, dinv, cur=0, and re-zeroes cnt for the next replay.
// g_sstat arrives zeroed (module init on call 1; reset by k_fill after).
// ---------------------------------------------------------------------------
__global__ void __launch_bounds__(256) k_scan_lb(
    int* __restrict__ cnt, int* __restrict__ offs, int* __restrict__ deg,
    int* __restrict__ cur, float* __restrict__ dinv, int n)
{
    __shared__ int ws[8];
    __shared__ int sprefix;
    int tid = threadIdx.x, lane = tid & 31, wid = tid >> 5;
    int bid = blockIdx.x;
    int i = bid * 256 + tid;

    int v = (i < n) ? cnt[i] : 0;
    int s = warp_iscan(v, lane);
    if (lane == 31) ws[wid] = s;
    __syncthreads();
    if (wid == 0) {
        int t = (lane < 8) ? ws[lane] : 0;
        t = warp_iscan(t, lane);
        if (lane < 8) ws[lane] = t;
    }
    __syncthreads();
    int base = wid ? ws[wid - 1] : 0;
    int total = ws[7];

    if (tid == 0) {
        if (bid == 0) {
            g_spre[0] = total;
            __threadfence();
            g_sstat[0] = 2;
            sprefix = 0;
        } else {
            g_sagg[bid] = total;
            __threadfence();
            g_sstat[bid] = 1;
            int run = 0;
            for (int j = bid - 1; j >= 0; j--) {
                int st;
                while ((st = g_sstat[j]) == 0) {}
                __threadfence();
                if (st == 2) { run += g_spre[j]; break; }
                run += g_sagg[j];
            }
            g_spre[bid] = run + total;
            __threadfence();
            g_sstat[bid] = 2;
            sprefix = run;
        }
    }
    __syncthreads();
    int pre = sprefix;

    if (i < n) {
        offs[i] = pre + base + s - v;   // exclusive
        deg[i]  = v;
        cur[i]  = 0;
        cnt[i]  = 0;                    // ready for next replay's histogram
        dinv[i] = rsqrtf((float)v + 1.0f);  // +1 self loop
    }
}

// ---------------------------------------------------------------------------
// CSR fill; also resets lookback status flags for the next replay.
// ---------------------------------------------------------------------------
__global__ void k_fill(const int* __restrict__ src, const int* __restrict__ dst,
                       const int* __restrict__ offs, int* cur, int* csr, int E, int n) {
    int e = blockIdx.x * blockDim.x + threadIdx.x;
    if (e < 256) g_sstat[e] = 0;
    if (e < E) {
        int d = dst[e];
        int s = src[e];
        if ((unsigned)d < (unsigned)n && (unsigned)s < (unsigned)n) {
            int p = offs[d] + atomicAdd(&cur[d], 1);
            csr[p] = s;
        }
    }
}

// ---------------------------------------------------------------------------
// CSR gather-reduce + fused epilogue: out = relu?((u[i] + sum u[src])*dinv + b)
// ---------------------------------------------------------------------------
__global__ void __launch_bounds__(256) k_gather(
    const float* __restrict__ u, const int* __restrict__ csr,
    const int* __restrict__ offs, const int* __restrict__ deg,
    const float* __restrict__ dinv, const float* __restrict__ b,
    float* __restrict__ out, int n, int relu)
{
    int node = (blockIdx.x * 256 + threadIdx.x) >> 5;
    if (node >= n) return;
    int lane = threadIdx.x & 31;
    int j4 = lane << 2;

    float4 acc = *(const float4*)(u + (size_t)node * 128 + j4);
    int beg = offs[node];
    int m = deg[node];

    for (int base = 0; base < m; base += 32) {
        int rem = min(32, m - base);
        int s = (base + lane < m) ? __ldg(&csr[beg + base + lane]) : 0;
#pragma unroll 4
        for (int j = 0; j < rem; j++) {
            int sj = __shfl_sync(0xffffffff, s, j);
            float4 v = *(const float4*)(u + (size_t)sj * 128 + j4);
            acc.x += v.x; acc.y += v.y; acc.z += v.z; acc.w += v.w;
        }
    }

    float di = dinv[node];
    float4 bb = *(const float4*)(b + j4);
    acc.x = acc.x * di + bb.x;
    acc.y = acc.y * di + bb.y;
    acc.z = acc.z * di + bb.z;
    acc.w = acc.w * di + bb.w;
    if (relu) {
        acc.x = fmaxf(acc.x, 0.f); acc.y = fmaxf(acc.y, 0.f);
        acc.z = fmaxf(acc.z, 0.f); acc.w = fmaxf(acc.w, 0.f);
    }
    *(float4*)(out + (size_t)node * 128 + j4) = acc;
}

// ---------------------------------------------------------------------------
extern "C" void kernel_launch(void* const* d_in, const int* in_sizes, int n_in,
                              void* d_out, int out_size)
{
    const float* x  = (const float*)d_in[0];
    const int*   ei = (const int*)d_in[1];     // int32 (JAX x64 disabled)
    const float* W0 = (const float*)d_in[2];
    const float* b0 = (const float*)d_in[3];
    const float* W1 = (const float*)d_in[4];
    const float* b1 = (const float*)d_in[5];
    const float* Wv = (const float*)d_in[6];
    const float* bv = (const float*)d_in[7];
    const float* Wt = (const float*)d_in[8];
    const float* bt = (const float*)d_in[9];

    int n = in_sizes[0] / Dd;
    int E = in_sizes[1] / 2;
    if (E > EMAX) E = EMAX;
    const int* srcp = ei;
    const int* dstp = ei + E;

    float* out_h = (float*)d_out;
    float* out_v = out_h + (size_t)n * Dd;
    float* out_t = out_v + (size_t)n * Dd;

    float *u, *h, *dinv, *wt;
    int *cnt, *deg, *offs, *cur, *csr;
    cudaGetSymbolAddress((void**)&u,    g_u);
    cudaGetSymbolAddress((void**)&h,    g_h);
    cudaGetSymbolAddress((void**)&dinv, g_dinv);
    cudaGetSymbolAddress((void**)&wt,   g_wt);
    cudaGetSymbolAddress((void**)&cnt,  g_cnt);
    cudaGetSymbolAddress((void**)&deg,  g_deg);
    cudaGetSymbolAddress((void**)&offs, g_offs);
    cudaGetSymbolAddress((void**)&cur,  g_cur);
    cudaGetSymbolAddress((void**)&csr,  g_csr);

    float* wt0 = wt;
    float* wt1 = wt + Dd * Dd;
    float* wtv = wt + 2 * Dd * Dd;
    float* wtt = wt + 3 * Dd * Dd;

    const int SMEM_GEMM = 128 * PADW * 4;   // 69632 bytes (W only)

    static bool attr_set = false;
    if (!attr_set) {
        cudaFuncSetAttribute(k_mma_gemm, cudaFuncAttributeMaxDynamicSharedMemorySize, SMEM_GEMM);
        attr_set = true;
    }

    int nb256 = (n + 255) / 256;
    int eb256 = (E + 255) / 256;
    int gathB = (n * 32 + 255) / 256;
    const int GEMMB = 296;   // persistent: 2 blocks/SM on 148 SMs

    // CSR build: 3 launches (prep+hist fused; single-pass lookback scan; fill)
    k_prep_hist<<<eb256, 256>>>(W0, W1, Wv, Wt, wt, dstp, cnt, E, n);
    k_scan_lb<<<nb256, 256>>>(cnt, offs, deg, cur, dinv, n);
    k_fill<<<eb256, 256>>>(srcp, dstp, offs, cur, csr, E, n);

    // layer 0
    k_mma_gemm<<<GEMMB, 256, SMEM_GEMM>>>(x, wt0, dinv, u,
                                          nullptr, nullptr, nullptr, n, 0, 1);
    k_gather<<<gathB, 256>>>(u, csr, offs, deg, dinv, b0, h, n, 1);

    // layer 1 (no relu), writes into d_out
    k_mma_gemm<<<GEMMB, 256, SMEM_GEMM>>>(h, wt1, dinv, u,
                                          nullptr, nullptr, nullptr, n, 0, 1);
    k_gather<<<gathB, 256>>>(u, csr, offs, deg, dinv, b1, out_h, n, 0);

    // both heads, one persistent launch (block parity selects head)
    k_mma_gemm<<<GEMMB, 256, SMEM_GEMM>>>(out_h, wtv, bv, out_v,
                                          wtt, bt, out_t, n, 1, 2);
}

// round 13
// speedup vs baseline: 1.0855x; 1.0855x over previous
#include <cuda_runtime.h>
#include <cstdint>

#define Dd 128
#define NMAX 50000
#define EMAX 1000000
#define PADW 144   // W smem row stride (words); (4*bn0+kq)%8 distinct per phase -> conflict-free LDS.128

// Scratch (static device globals -- no allocation allowed)
__device__ float g_u[NMAX * Dd];
__device__ float g_h[NMAX * Dd];
__device__ float g_dinv[NMAX];
__device__ float g_wt[4][Dd * Dd];   // transposed + tf32 weights [N][K] (natural k order)
__device__ int   g_cnt[NMAX];
__device__ int   g_deg[NMAX];
__device__ int   g_offs[NMAX];
__device__ int   g_cur[NMAX];
__device__ int   g_csr[EMAX];
__device__ int   g_bsum[256];

__device__ __forceinline__ uint32_t f2tf32(float v) {
    uint32_t r;
    asm("cvt.rna.tf32.f32 %0, %1;" : "=r"(r) : "f"(v));
    return r;
}

__device__ __forceinline__ void mma_tf32(float c[4], uint32_t a0, uint32_t a1,
                                         uint32_t a2, uint32_t a3,
                                         uint32_t b0, uint32_t b1) {
    asm volatile(
        "mma.sync.aligned.m16n8k8.row.col.f32.tf32.tf32.f32 "
        "{%0,%1,%2,%3}, {%4,%5,%6,%7}, {%8,%9}, {%0,%1,%2,%3};"
        : "+f"(c[0]), "+f"(c[1]), "+f"(c[2]), "+f"(c[3])
        : "r"(a0), "r"(a1), "r"(a2), "r"(a3), "r"(b0), "r"(b1));
}

__device__ __forceinline__ int warp_iscan(int v, int lane) {
#pragma unroll
    for (int d = 1; d < 32; d <<= 1) {
        int t = __shfl_up_sync(0xffffffff, v, d);
        if (lane >= d) v += t;
    }
    return v;
}

__device__ __forceinline__ float4 ldg4z(const float* p, bool v) {
    if (v) return __ldg((const float4*)p);
    return make_float4(0.f, 0.f, 0.f, 0.f);
}

// ---------------------------------------------------------------------------
// Persistent tf32 mma.sync GEMM. A: one LDG.128 per 16-k supergroup per row
// (lane quad kq owns cols 4kq..4kq+3), pipelined one supergroup ahead.
// B: one LDS.128 per nt per supergroup from NATURAL-layout W smem --
// the fragment algebra makes lane kq's four B words exactly cols 4kq..4kq+3.
//  mode 0: aux=dinv -> C = val*dinv[row]
//  mode 1: aux=bias -> C = relu(val + bias)
//  nheads==2: block parity selects (Wt1,aux1,C1)
// ---------------------------------------------------------------------------
__global__ void __launch_bounds__(256, 2) k_mma_gemm(
    const float* __restrict__ A,
    const float* __restrict__ Wt0, const float* __restrict__ aux0, float* __restrict__ C0,
    const float* Wt1, const float* aux1, float* C1,
    int n, int mode, int nheads)
{
    extern __shared__ float sm[];
    uint32_t* Wsu = (uint32_t*)sm;   // [128][PADW]

    int tid  = threadIdx.x;
    int wid  = tid >> 5;
    int lane = tid & 31;

    int ntiles = (n + 127) >> 7;
    int tile0, tstep;
    const float* Wt; const float* aux; float* C;
    if (nheads == 2) {
        int head = blockIdx.x & 1;
        tile0 = blockIdx.x >> 1;
        tstep = gridDim.x >> 1;
        Wt = head ? Wt1 : Wt0; aux = head ? aux1 : aux0; C = head ? C1 : C0;
    } else {
        tile0 = blockIdx.x;
        tstep = gridDim.x;
        Wt = Wt0; aux = aux0; C = C0;
    }

    const uint4* Wt4 = (const uint4*)Wt;
#pragma unroll
    for (int i = 0; i < 16; i++) {
        int f = tid + i * 256;
        int r = f >> 5, j = (f & 31) << 2;
        *(uint4*)(Wsu + r * PADW + j) = Wt4[f];
    }
    __syncthreads();

    int kq  = lane & 3;
    int bn0 = lane >> 2;

    for (int tile = tile0; tile < ntiles; tile += tstep) {
        int row0 = tile << 7;
        int r0 = row0 + wid * 16 + (lane >> 2);
        int r1 = r0 + 8;
        bool v0 = r0 < n, v1 = r1 < n;
        const float* a0p = A + (size_t)r0 * 128 + (kq << 2);
        const float* a1p = a0p + 8 * 128;

        float c[16][4];
#pragma unroll
        for (int nt = 0; nt < 16; nt++)
#pragma unroll
            for (int q = 0; q < 4; q++) c[nt][q] = 0.0f;

        float4 fA = ldg4z(a0p, v0);
        float4 fB = ldg4z(a1p, v1);

#pragma unroll
        for (int G = 0; G < 8; G++) {
            float4 nA, nB;
            if (G < 7) {
                nA = ldg4z(a0p + (G + 1) * 16, v0);
                nB = ldg4z(a1p + (G + 1) * 16, v1);
            }
            uint32_t a00 = f2tf32(fA.x), a10 = f2tf32(fB.x);
            uint32_t a20 = f2tf32(fA.y), a30 = f2tf32(fB.y);
            uint32_t a01 = f2tf32(fA.z), a11 = f2tf32(fB.z);
            uint32_t a21 = f2tf32(fA.w), a31 = f2tf32(fB.w);
            int gbase = G * 16 + (kq << 2);
#pragma unroll
            for (int nt = 0; nt < 16; nt++) {
                uint4 b = *(const uint4*)(Wsu + (nt * 8 + bn0) * PADW + gbase);
                mma_tf32(c[nt], a00, a10, a20, a30, b.x, b.y);
                mma_tf32(c[nt], a01, a11, a21, a31, b.z, b.w);
            }
            fA = nA; fB = nB;
        }

        int cc = kq * 2;
        if (mode == 0) {
            float d0 = v0 ? aux[r0] : 0.0f;
            float d1 = v1 ? aux[r1] : 0.0f;
#pragma unroll
            for (int nt = 0; nt < 16; nt++) {
                int col = nt * 8 + cc;
                if (v0)
                    *(float2*)(C + (size_t)r0 * 128 + col) =
                        make_float2(c[nt][0] * d0, c[nt][1] * d0);
                if (v1)
                    *(float2*)(C + (size_t)r1 * 128 + col) =
                        make_float2(c[nt][2] * d1, c[nt][3] * d1);
            }
        } else {
#pragma unroll
            for (int nt = 0; nt < 16; nt++) {
                int col = nt * 8 + cc;
                float2 bb = *(const float2*)(aux + col);
                if (v0)
                    *(float2*)(C + (size_t)r0 * 128 + col) =
                        make_float2(fmaxf(c[nt][0] + bb.x, 0.f), fmaxf(c[nt][1] + bb.y, 0.f));
                if (v1)
                    *(float2*)(C + (size_t)r1 * 128 + col) =
                        make_float2(fmaxf(c[nt][2] + bb.x, 0.f), fmaxf(c[nt][3] + bb.y, 0.f));
            }
        }
    }
}

// ---------------------------------------------------------------------------
// prep: Wt[w][n][k] = tf32(W[k][n]) (natural k order); zero cnt[]
// ---------------------------------------------------------------------------
__global__ void k_prep(const float* __restrict__ W0, const float* __restrict__ W1,
                       const float* __restrict__ W2, const float* __restrict__ W3,
                       float* __restrict__ Wt, int* __restrict__ cnt, int n) {
    int i = blockIdx.x * blockDim.x + threadIdx.x;
    if (i < 4 * Dd * Dd) {
        int w = i >> 14, r = i & (Dd * Dd - 1);
        const float* W = (w == 0) ? W0 : (w == 1) ? W1 : (w == 2) ? W2 : W3;
        int k = r >> 7, nn = r & 127;
        ((uint32_t*)Wt)[w * Dd * Dd + nn * Dd + k] = f2tf32(W[k * Dd + nn]);
    }
    if (i < n) cnt[i] = 0;
}

// ---------------------------------------------------------------------------
// CSR build (R10-proven chain)
// ---------------------------------------------------------------------------
__global__ void k_hist(const int* __restrict__ dst, int* cnt, int E, int n) {
    int e = blockIdx.x * blockDim.x + threadIdx.x;
    if (e < E) {
        int d = dst[e];
        if ((unsigned)d < (unsigned)n) atomicAdd(&cnt[d], 1);
    }
}

__global__ void k_scan1(const int* __restrict__ cnt, int* offs, int* bsum, int n) {
    __shared__ int ws[8];
    int tid = threadIdx.x, lane = tid & 31, wid = tid >> 5;
    int i = blockIdx.x * 256 + tid;
    int v = (i < n) ? cnt[i] : 0;
    int s = warp_iscan(v, lane);
    if (lane == 31) ws[wid] = s;
    __syncthreads();
    if (wid == 0) {
        int t = (lane < 8) ? ws[lane] : 0;
        t = warp_iscan(t, lane);
        if (lane < 8) ws[lane] = t;
    }
    __syncthreads();
    int base = wid ? ws[wid - 1] : 0;
    if (i < n) offs[i] = base + s - v;
    if (tid == 255) bsum[blockIdx.x] = base + s;
}

// scan2+scan3 merged: each block reduces bsum[0..blockIdx.x) itself
__global__ void k_scan23(int* offs, const int* __restrict__ bsum,
                         const int* __restrict__ cnt, int* cur, int* deg,
                         float* dinv, int n) {
    __shared__ int ws[8];
    int tid = threadIdx.x, lane = tid & 31, wid = tid >> 5;
    int v = (tid < (int)blockIdx.x) ? bsum[tid] : 0;   // gridDim <= 256
#pragma unroll
    for (int d = 16; d > 0; d >>= 1) v += __shfl_down_sync(0xffffffff, v, d);
    if (lane == 0) ws[wid] = v;
    __syncthreads();
    if (tid == 0) {
        int t = 0;
#pragma unroll
        for (int q = 0; q < 8; q++) t += ws[q];
        ws[0] = t;
    }
    __syncthreads();
    int pre = ws[0];
    int i = blockIdx.x * 256 + tid;
    if (i < n) {
        offs[i] += pre;
        cur[i] = 0;
        int dv = cnt[i];
        deg[i] = dv;
        dinv[i] = rsqrtf((float)dv + 1.0f);  // +1 self loop
    }
}

__global__ void k_fill(const int* __restrict__ src, const int* __restrict__ dst,
                       const int* __restrict__ offs, int* cur, int* csr, int E, int n) {
    int e = blockIdx.x * blockDim.x + threadIdx.x;
    if (e < E) {
        int d = dst[e];
        int s = src[e];
        if ((unsigned)d < (unsigned)n && (unsigned)s < (unsigned)n) {
            int p = offs[d] + atomicAdd(&cur[d], 1);
            csr[p] = s;
        }
    }
}

// ---------------------------------------------------------------------------
// CSR gather-reduce + fused epilogue: out = relu?((u[i] + sum u[src])*dinv + b)
// ---------------------------------------------------------------------------
__global__ void __launch_bounds__(256) k_gather(
    const float* __restrict__ u, const int* __restrict__ csr,
    const int* __restrict__ offs, const int* __restrict__ deg,
    const float* __restrict__ dinv, const float* __restrict__ b,
    float* __restrict__ out, int n, int relu)
{
    int node = (blockIdx.x * 256 + threadIdx.x) >> 5;
    if (node >= n) return;
    int lane = threadIdx.x & 31;
    int j4 = lane << 2;

    float4 acc = *(const float4*)(u + (size_t)node * 128 + j4);
    int beg = offs[node];
    int m = deg[node];

    for (int base = 0; base < m; base += 32) {
        int rem = min(32, m - base);
        int s = (base + lane < m) ? __ldg(&csr[beg + base + lane]) : 0;
#pragma unroll 4
        for (int j = 0; j < rem; j++) {
            int sj = __shfl_sync(0xffffffff, s, j);
            float4 v = *(const float4*)(u + (size_t)sj * 128 + j4);
            acc.x += v.x; acc.y += v.y; acc.z += v.z; acc.w += v.w;
        }
    }

    float di = dinv[node];
    float4 bb = *(const float4*)(b + j4);
    acc.x = acc.x * di + bb.x;
    acc.y = acc.y * di + bb.y;
    acc.z = acc.z * di + bb.z;
    acc.w = acc.w * di + bb.w;
    if (relu) {
        acc.x = fmaxf(acc.x, 0.f); acc.y = fmaxf(acc.y, 0.f);
        acc.z = fmaxf(acc.z, 0.f); acc.w = fmaxf(acc.w, 0.f);
    }
    *(float4*)(out + (size_t)node * 128 + j4) = acc;
}

// ---------------------------------------------------------------------------
extern "C" void kernel_launch(void* const* d_in, const int* in_sizes, int n_in,
                              void* d_out, int out_size)
{
    const float* x  = (const float*)d_in[0];
    const int*   ei = (const int*)d_in[1];     // int32 (JAX x64 disabled)
    const float* W0 = (const float*)d_in[2];
    const float* b0 = (const float*)d_in[3];
    const float* W1 = (const float*)d_in[4];
    const float* b1 = (const float*)d_in[5];
    const float* Wv = (const float*)d_in[6];
    const float* bv = (const float*)d_in[7];
    const float* Wt = (const float*)d_in[8];
    const float* bt = (const float*)d_in[9];

    int n = in_sizes[0] / Dd;
    int E = in_sizes[1] / 2;
    if (E > EMAX) E = EMAX;
    const int* srcp = ei;
    const int* dstp = ei + E;

    float* out_h = (float*)d_out;
    float* out_v = out_h + (size_t)n * Dd;
    float* out_t = out_v + (size_t)n * Dd;

    float *u, *h, *dinv, *wt;
    int *cnt, *deg, *offs, *cur, *csr, *bsum;
    cudaGetSymbolAddress((void**)&u,    g_u);
    cudaGetSymbolAddress((void**)&h,    g_h);
    cudaGetSymbolAddress((void**)&dinv, g_dinv);
    cudaGetSymbolAddress((void**)&wt,   g_wt);
    cudaGetSymbolAddress((void**)&cnt,  g_cnt);
    cudaGetSymbolAddress((void**)&deg,  g_deg);
    cudaGetSymbolAddress((void**)&offs, g_offs);
    cudaGetSymbolAddress((void**)&cur,  g_cur);
    cudaGetSymbolAddress((void**)&csr,  g_csr);
    cudaGetSymbolAddress((void**)&bsum, g_bsum);

    float* wt0 = wt;
    float* wt1 = wt + Dd * Dd;
    float* wtv = wt + 2 * Dd * Dd;
    float* wtt = wt + 3 * Dd * Dd;

    const int SMEM_GEMM = 128 * PADW * 4;   // 73728 bytes (W only); 2 blocks/SM

    static bool attr_set = false;
    if (!attr_set) {
        cudaFuncSetAttribute(k_mma_gemm, cudaFuncAttributeMaxDynamicSharedMemorySize, SMEM_GEMM);
        attr_set = true;
    }

    int nb256 = (n + 255) / 256;
    int eb256 = (E + 255) / 256;
    int gathB = (n * 32 + 255) / 256;
    int prepB = (4 * Dd * Dd + 255) / 256;
    const int GEMMB = 296;   // persistent: 2 blocks/SM on 148 SMs

    // prep + CSR build (R10 chain)
    k_prep<<<prepB, 256>>>(W0, W1, Wv, Wt, wt, cnt, n);
    k_hist<<<eb256, 256>>>(dstp, cnt, E, n);
    k_scan1<<<nb256, 256>>>(cnt, offs, bsum, n);
    k_scan23<<<nb256, 256>>>(offs, bsum, cnt, cur, deg, dinv, n);
    k_fill<<<eb256, 256>>>(srcp, dstp, offs, cur, csr, E, n);

    // layer 0
    k_mma_gemm<<<GEMMB, 256, SMEM_GEMM>>>(x, wt0, dinv, u,
                                          nullptr, nullptr, nullptr, n, 0, 1);
    k_gather<<<gathB, 256>>>(u, csr, offs, deg, dinv, b0, h, n, 1);

    // layer 1 (no relu), writes into d_out
    k_mma_gemm<<<GEMMB, 256, SMEM_GEMM>>>(h, wt1, dinv, u,
                                          nullptr, nullptr, nullptr, n, 0, 1);
    k_gather<<<gathB, 256>>>(u, csr, offs, deg, dinv, b1, out_h, n, 0);

    // both heads, one persistent launch (block parity selects head)
    k_mma_gemm<<<GEMMB, 256, SMEM_GEMM>>>(out_h, wtv, bv, out_v,
                                          wtt, bt, out_t, n, 1, 2);
}

// round 14
// speedup vs baseline: 1.1286x; 1.0397x over previous
#include <cuda_runtime.h>
#include <cstdint>

#define Dd 128
#define NMAX 50000
#define EMAX 1000000
#define PADW 136   // W smem row stride (words); conflict-free per half-warp phase

// Scratch (static device globals -- no allocation allowed)
__device__ float g_u[NMAX * Dd];
__device__ float g_h[NMAX * Dd];
__device__ float g_dinv[NMAX];
__device__ float g_wt[4][Dd * Dd];   // transposed + tf32 + k-permuted weights [N][K']
__device__ int   g_cnt[NMAX];
__device__ int   g_deg[NMAX];
__device__ int   g_offs[NMAX];
__device__ int   g_cur[NMAX];
__device__ int   g_csr[EMAX];
__device__ int   g_bsum[256];

__device__ __forceinline__ uint32_t f2tf32(float v) {
    uint32_t r;
    asm("cvt.rna.tf32.f32 %0, %1;" : "=r"(r) : "f"(v));
    return r;
}

__device__ __forceinline__ void mma_tf32(float c[4], uint32_t a0, uint32_t a1,
                                         uint32_t a2, uint32_t a3,
                                         uint32_t b0, uint32_t b1) {
    asm volatile(
        "mma.sync.aligned.m16n8k8.row.col.f32.tf32.tf32.f32 "
        "{%0,%1,%2,%3}, {%4,%5,%6,%7}, {%8,%9}, {%0,%1,%2,%3};"
        : "+f"(c[0]), "+f"(c[1]), "+f"(c[2]), "+f"(c[3])
        : "r"(a0), "r"(a1), "r"(a2), "r"(a3), "r"(b0), "r"(b1));
}

__device__ __forceinline__ int warp_iscan(int v, int lane) {
#pragma unroll
    for (int d = 1; d < 32; d <<= 1) {
        int t = __shfl_up_sync(0xffffffff, v, d);
        if (lane >= d) v += t;
    }
    return v;
}

__device__ __forceinline__ float4 ldg4z(const float* p, bool v) {
    if (v) return __ldg((const float4*)p);
    return make_float4(0.f, 0.f, 0.f, 0.f);
}

// ---------------------------------------------------------------------------
// Persistent tf32 mma.sync GEMM (R10 config: permuted W, uint2 B-frags)
// with A prefetch depth 2 (load supergroup G+2 while computing G).
//  mode 0: aux=dinv -> C = val*dinv[row]
//  mode 1: aux=bias -> C = relu(val + bias)
//  nheads==2: block parity selects (Wt1,aux1,C1)
// ---------------------------------------------------------------------------
__global__ void __launch_bounds__(256, 2) k_mma_gemm(
    const float* __restrict__ A,
    const float* __restrict__ Wt0, const float* __restrict__ aux0, float* __restrict__ C0,
    const float* Wt1, const float* aux1, float* C1,
    int n, int mode, int nheads)
{
    extern __shared__ float sm[];
    uint32_t* Wsu = (uint32_t*)sm;   // [128][PADW]

    int tid  = threadIdx.x;
    int wid  = tid >> 5;
    int lane = tid & 31;

    int ntiles = (n + 127) >> 7;
    int tile0, tstep;
    const float* Wt; const float* aux; float* C;
    if (nheads == 2) {
        int head = blockIdx.x & 1;
        tile0 = blockIdx.x >> 1;
        tstep = gridDim.x >> 1;
        Wt = head ? Wt1 : Wt0; aux = head ? aux1 : aux0; C = head ? C1 : C0;
    } else {
        tile0 = blockIdx.x;
        tstep = gridDim.x;
        Wt = Wt0; aux = aux0; C = C0;
    }

    const uint4* Wt4 = (const uint4*)Wt;
#pragma unroll
    for (int i = 0; i < 16; i++) {
        int f = tid + i * 256;
        int r = f >> 5, j = (f & 31) << 2;
        *(uint4*)(Wsu + r * PADW + j) = Wt4[f];
    }
    __syncthreads();

    int kq  = lane & 3;
    int bn0 = lane >> 2;

    for (int tile = tile0; tile < ntiles; tile += tstep) {
        int row0 = tile << 7;
        int r0 = row0 + wid * 16 + (lane >> 2);
        int r1 = r0 + 8;
        bool v0 = r0 < n, v1 = r1 < n;
        const float* a0p = A + (size_t)r0 * 128 + (kq << 2);
        const float* a1p = a0p + 8 * 128;

        float c[16][4];
#pragma unroll
        for (int nt = 0; nt < 16; nt++)
#pragma unroll
            for (int q = 0; q < 4; q++) c[nt][q] = 0.0f;

        // prefetch depth 2: buffers for G and G+1 in flight
        float4 bA0 = ldg4z(a0p,      v0);
        float4 bB0 = ldg4z(a1p,      v1);
        float4 bA1 = ldg4z(a0p + 16, v0);
        float4 bB1 = ldg4z(a1p + 16, v1);

#pragma unroll
        for (int G = 0; G < 8; G++) {
            float4 fA = (G & 1) ? bA1 : bA0;
            float4 fB = (G & 1) ? bB1 : bB0;
            float4 nA, nB;
            if (G < 6) {
                nA = ldg4z(a0p + (G + 2) * 16, v0);
                nB = ldg4z(a1p + (G + 2) * 16, v1);
            }
            uint32_t a00 = f2tf32(fA.x), a10 = f2tf32(fB.x);
            uint32_t a20 = f2tf32(fA.y), a30 = f2tf32(fB.y);
            uint32_t a01 = f2tf32(fA.z), a11 = f2tf32(fB.z);
            uint32_t a21 = f2tf32(fA.w), a31 = f2tf32(fB.w);
            int gbase = G * 16 + (kq << 1);
#pragma unroll
            for (int nt = 0; nt < 16; nt++) {
                const uint32_t* wr = Wsu + (nt * 8 + bn0) * PADW + gbase;
                uint2 b0 = *(const uint2*)wr;
                uint2 b1 = *(const uint2*)(wr + 8);
                mma_tf32(c[nt], a00, a10, a20, a30, b0.x, b0.y);
                mma_tf32(c[nt], a01, a11, a21, a31, b1.x, b1.y);
            }
            if (G & 1) { bA1 = nA; bB1 = nB; } else { bA0 = nA; bB0 = nB; }
        }

        int cc = kq * 2;
        if (mode == 0) {
            float d0 = v0 ? aux[r0] : 0.0f;
            float d1 = v1 ? aux[r1] : 0.0f;
#pragma unroll
            for (int nt = 0; nt < 16; nt++) {
                int col = nt * 8 + cc;
                if (v0)
                    *(float2*)(C + (size_t)r0 * 128 + col) =
                        make_float2(c[nt][0] * d0, c[nt][1] * d0);
                if (v1)
                    *(float2*)(C + (size_t)r1 * 128 + col) =
                        make_float2(c[nt][2] * d1, c[nt][3] * d1);
            }
        } else {
#pragma unroll
            for (int nt = 0; nt < 16; nt++) {
                int col = nt * 8 + cc;
                float2 bb = *(const float2*)(aux + col);
                if (v0)
                    *(float2*)(C + (size_t)r0 * 128 + col) =
                        make_float2(fmaxf(c[nt][0] + bb.x, 0.f), fmaxf(c[nt][1] + bb.y, 0.f));
                if (v1)
                    *(float2*)(C + (size_t)r1 * 128 + col) =
                        make_float2(fmaxf(c[nt][2] + bb.x, 0.f), fmaxf(c[nt][3] + bb.y, 0.f));
            }
        }
    }
}

// ---------------------------------------------------------------------------
// prep: Wt[w][n][perm(k)] = tf32(W[k][n]); zero cnt[]
// perm within 16-group: kq=(k>>2)&3, s=(k>>1)&1, t=k&1 -> (s<<3)|(kq<<1)|t
// ---------------------------------------------------------------------------
__global__ void k_prep(const float* __restrict__ W0, const float* __restrict__ W1,
                       const float* __restrict__ W2, const float* __restrict__ W3,
                       float* __restrict__ Wt, int* __restrict__ cnt, int n) {
    int i = blockIdx.x * blockDim.x + threadIdx.x;
    if (i < 4 * Dd * Dd) {
        int w = i >> 14, r = i & (Dd * Dd - 1);
        const float* W = (w == 0) ? W0 : (w == 1) ? W1 : (w == 2) ? W2 : W3;
        int k = r >> 7, nn = r & 127;
        int kp = (k & ~15) | (((k >> 1) & 1) << 3) | (((k >> 2) & 3) << 1) | (k & 1);
        ((uint32_t*)Wt)[w * Dd * Dd + nn * Dd + kp] = f2tf32(W[k * Dd + nn]);
    }
    if (i < n) cnt[i] = 0;
}

// ---------------------------------------------------------------------------
// CSR build (R10-proven chain)
// ---------------------------------------------------------------------------
__global__ void k_hist(const int* __restrict__ dst, int* cnt, int E, int n) {
    int e = blockIdx.x * blockDim.x + threadIdx.x;
    if (e < E) {
        int d = dst[e];
        if ((unsigned)d < (unsigned)n) atomicAdd(&cnt[d], 1);
    }
}

__global__ void k_scan1(const int* __restrict__ cnt, int* offs, int* bsum, int n) {
    __shared__ int ws[8];
    int tid = threadIdx.x, lane = tid & 31, wid = tid >> 5;
    int i = blockIdx.x * 256 + tid;
    int v = (i < n) ? cnt[i] : 0;
    int s = warp_iscan(v, lane);
    if (lane == 31) ws[wid] = s;
    __syncthreads();
    if (wid == 0) {
        int t = (lane < 8) ? ws[lane] : 0;
        t = warp_iscan(t, lane);
        if (lane < 8) ws[lane] = t;
    }
    __syncthreads();
    int base = wid ? ws[wid - 1] : 0;
    if (i < n) offs[i] = base + s - v;
    if (tid == 255) bsum[blockIdx.x] = base + s;
}

// scan2+scan3 merged: each block reduces bsum[0..blockIdx.x) itself
__global__ void k_scan23(int* offs, const int* __restrict__ bsum,
                         const int* __restrict__ cnt, int* cur, int* deg,
                         float* dinv, int n) {
    __shared__ int ws[8];
    int tid = threadIdx.x, lane = tid & 31, wid = tid >> 5;
    int v = (tid < (int)blockIdx.x) ? bsum[tid] : 0;   // gridDim <= 256
#pragma unroll
    for (int d = 16; d > 0; d >>= 1) v += __shfl_down_sync(0xffffffff, v, d);
    if (lane == 0) ws[wid] = v;
    __syncthreads();
    if (tid == 0) {
        int t = 0;
#pragma unroll
        for (int q = 0; q < 8; q++) t += ws[q];
        ws[0] = t;
    }
    __syncthreads();
    int pre = ws[0];
    int i = blockIdx.x * 256 + tid;
    if (i < n) {
        offs[i] += pre;
        cur[i] = 0;
        int dv = cnt[i];
        deg[i] = dv;
        dinv[i] = rsqrtf((float)dv + 1.0f);  // +1 self loop
    }
}

__global__ void k_fill(const int* __restrict__ src, const int* __restrict__ dst,
                       const int* __restrict__ offs, int* cur, int* csr, int E, int n) {
    int e = blockIdx.x * blockDim.x + threadIdx.x;
    if (e < E) {
        int d = dst[e];
        int s = src[e];
        if ((unsigned)d < (unsigned)n && (unsigned)s < (unsigned)n) {
            int p = offs[d] + atomicAdd(&cur[d], 1);
            csr[p] = s;
        }
    }
}

// ---------------------------------------------------------------------------
// CSR gather-reduce + fused epilogue: out = relu?((u[i] + sum u[src])*dinv + b)
// ---------------------------------------------------------------------------
__global__ void __launch_bounds__(256) k_gather(
    const float* __restrict__ u, const int* __restrict__ csr,
    const int* __restrict__ offs, const int* __restrict__ deg,
    const float* __restrict__ dinv, const float* __restrict__ b,
    float* __restrict__ out, int n, int relu)
{
    int node = (blockIdx.x * 256 + threadIdx.x) >> 5;
    if (node >= n) return;
    int lane = threadIdx.x & 31;
    int j4 = lane << 2;

    float4 acc = *(const float4*)(u + (size_t)node * 128 + j4);
    int beg = offs[node];
    int m = deg[node];

    for (int base = 0; base < m; base += 32) {
        int rem = min(32, m - base);
        int s = (base + lane < m) ? __ldg(&csr[beg + base + lane]) : 0;
#pragma unroll 4
        for (int j = 0; j < rem; j++) {
            int sj = __shfl_sync(0xffffffff, s, j);
            float4 v = *(const float4*)(u + (size_t)sj * 128 + j4);
            acc.x += v.x; acc.y += v.y; acc.z += v.z; acc.w += v.w;
        }
    }

    float di = dinv[node];
    float4 bb = *(const float4*)(b + j4);
    acc.x = acc.x * di + bb.x;
    acc.y = acc.y * di + bb.y;
    acc.z = acc.z * di + bb.z;
    acc.w = acc.w * di + bb.w;
    if (relu) {
        acc.x = fmaxf(acc.x, 0.f); acc.y = fmaxf(acc.y, 0.f);
        acc.z = fmaxf(acc.z, 0.f); acc.w = fmaxf(acc.w, 0.f);
    }
    *(float4*)(out + (size_t)node * 128 + j4) = acc;
}

// ---------------------------------------------------------------------------
extern "C" void kernel_launch(void* const* d_in, const int* in_sizes, int n_in,
                              void* d_out, int out_size)
{
    const float* x  = (const float*)d_in[0];
    const int*   ei = (const int*)d_in[1];     // int32 (JAX x64 disabled)
    const float* W0 = (const float*)d_in[2];
    const float* b0 = (const float*)d_in[3];
    const float* W1 = (const float*)d_in[4];
    const float* b1 = (const float*)d_in[5];
    const float* Wv = (const float*)d_in[6];
    const float* bv = (const float*)d_in[7];
    const float* Wt = (const float*)d_in[8];
    const float* bt = (const float*)d_in[9];

    int n = in_sizes[0] / Dd;
    int E = in_sizes[1] / 2;
    if (E > EMAX) E = EMAX;
    const int* srcp = ei;
    const int* dstp = ei + E;

    float* out_h = (float*)d_out;
    float* out_v = out_h + (size_t)n * Dd;
    float* out_t = out_v + (size_t)n * Dd;

    float *u, *h, *dinv, *wt;
    int *cnt, *deg, *offs, *cur, *csr, *bsum;
    cudaGetSymbolAddress((void**)&u,    g_u);
    cudaGetSymbolAddress((void**)&h,    g_h);
    cudaGetSymbolAddress((void**)&dinv, g_dinv);
    cudaGetSymbolAddress((void**)&wt,   g_wt);
    cudaGetSymbolAddress((void**)&cnt,  g_cnt);
    cudaGetSymbolAddress((void**)&deg,  g_deg);
    cudaGetSymbolAddress((void**)&offs, g_offs);
    cudaGetSymbolAddress((void**)&cur,  g_cur);
    cudaGetSymbolAddress((void**)&csr,  g_csr);
    cudaGetSymbolAddress((void**)&bsum, g_bsum);

    float* wt0 = wt;
    float* wt1 = wt + Dd * Dd;
    float* wtv = wt + 2 * Dd * Dd;
    float* wtt = wt + 3 * Dd * Dd;

    const int SMEM_GEMM = 128 * PADW * 4;   // 69632 bytes (W only); 2 blocks/SM

    static bool attr_set = false;
    if (!attr_set) {
        cudaFuncSetAttribute(k_mma_gemm, cudaFuncAttributeMaxDynamicSharedMemorySize, SMEM_GEMM);
        attr_set = true;
    }

    int nb256 = (n + 255) / 256;
    int eb256 = (E + 255) / 256;
    int gathB = (n * 32 + 255) / 256;
    int prepB = (4 * Dd * Dd + 255) / 256;
    const int GEMMB = 296;   // persistent: 2 blocks/SM on 148 SMs

    // prep + CSR build (R10 chain)
    k_prep<<<prepB, 256>>>(W0, W1, Wv, Wt, wt, cnt, n);
    k_hist<<<eb256, 256>>>(dstp, cnt, E, n);
    k_scan1<<<nb256, 256>>>(cnt, offs, bsum, n);
    k_scan23<<<nb256, 256>>>(offs, bsum, cnt, cur, deg, dinv, n);
    k_fill<<<eb256, 256>>>(srcp, dstp, offs, cur, csr, E, n);

    // layer 0
    k_mma_gemm<<<GEMMB, 256, SMEM_GEMM>>>(x, wt0, dinv, u,
                                          nullptr, nullptr, nullptr, n, 0, 1);
    k_gather<<<gathB, 256>>>(u, csr, offs, deg, dinv, b0, h, n, 1);

    // layer 1 (no relu), writes into d_out
    k_mma_gemm<<<GEMMB, 256, SMEM_GEMM>>>(h, wt1, dinv, u,
                                          nullptr, nullptr, nullptr, n, 0, 1);
    k_gather<<<gathB, 256>>>(u, csr, offs, deg, dinv, b1, out_h, n, 0);

    // both heads, one persistent launch (block parity selects head)
    k_mma_gemm<<<GEMMB, 256, SMEM_GEMM>>>(out_h, wtv, bv, out_v,
                                          wtt, bt, out_t, n, 1, 2);
}